// round 1
// baseline (speedup 1.0000x reference)
#include <cuda_runtime.h>
#include <cuda_bf16.h>

#define N_NODES 100000
#define N_EDGES 1280000
#define HH 64
#define NL 5
#define N_GRAPHS 512

typedef unsigned long long ull;

// ---------------- static device scratch (no allocations allowed) ----------------
__device__ __align__(16) float d_z[N_NODES * HH];      // node features (layer input)
__device__ __align__(16) float d_hin[N_NODES * HH];    // z + aggr
__device__ __align__(16) float d_h1[N_NODES * 128];    // after Linear1
__device__ __align__(16) float d_h2[N_NODES * HH];     // after Linear2
__device__ __align__(16) float d_tab[512 * HH];        // bond-embedding table (8^3 codes)
__device__ int d_counts[N_NODES];
__device__ int d_rowstart[N_NODES + 1];
__device__ int d_cursor[N_NODES];
__device__ int d_csr_src[N_EDGES];
__device__ unsigned short d_code[N_EDGES];
__device__ unsigned short d_csr_code[N_EDGES];
__device__ float d_ssum[128];
__device__ float d_ssq[128];
__device__ float d_scale[128];
__device__ float d_shift[128];

// ---------------- packed f32x2 helpers ----------------
__device__ __forceinline__ ull pack2(float x, float y) {
    ull r; asm("mov.b64 %0, {%1, %2};" : "=l"(r) : "f"(x), "f"(y)); return r;
}
__device__ __forceinline__ void fma2u(ull &d, ull a, ull b) {
    asm("fma.rn.f32x2 %0, %1, %2, %0;" : "+l"(d) : "l"(a), "l"(b));
}

// ---------------- precompute kernels ----------------
__global__ void zero_kernel() {
    int t = blockIdx.x * blockDim.x + threadIdx.x;
    for (int i = t; i < N_NODES; i += gridDim.x * blockDim.x) d_counts[i] = 0;
    if (t < 128) { d_ssum[t] = 0.f; d_ssq[t] = 0.f; }
}

__global__ void tab_kernel(const float* __restrict__ bond_emb) {
    int t = blockIdx.x * blockDim.x + threadIdx.x;  // 512*64 threads
    int q = t >> 6, c = t & 63;
    int a0 = q >> 6, a1 = (q >> 3) & 7, a2 = q & 7;
    d_tab[t] = bond_emb[(0 * 8 + a0) * HH + c]
             + bond_emb[(1 * 8 + a1) * HH + c]
             + bond_emb[(2 * 8 + a2) * HH + c];
}

__global__ void z0_kernel(const int* __restrict__ x, const float* __restrict__ atom_emb) {
    int t = blockIdx.x * blockDim.x + threadIdx.x;  // N*64
    int n = t >> 6, c = t & 63;
    float s = 0.f;
#pragma unroll
    for (int a = 0; a < 9; a++) {
        int idx = __ldg(&x[n * 9 + a]);
        s += __ldg(&atom_emb[(a * 128 + idx) * HH + c]);
    }
    d_z[t] = s;
}

__global__ void count_kernel(const int* __restrict__ ei, const int* __restrict__ ea) {
    int e = blockIdx.x * blockDim.x + threadIdx.x;  // E
    int a0 = ea[e * 3 + 0], a1 = ea[e * 3 + 1], a2 = ea[e * 3 + 2];
    d_code[e] = (unsigned short)((a0 << 6) | (a1 << 3) | a2);
    int dst = ei[N_EDGES + e];
    atomicAdd(&d_counts[dst], 1);
}

__global__ void scan_kernel() {
    __shared__ int wsum[32];
    __shared__ int s_carry;
    int tid = threadIdx.x, lane = tid & 31, wid = tid >> 5;
    if (tid == 0) s_carry = 0;
    __syncthreads();
    for (int base = 0; base < N_NODES; base += 1024) {
        int i = base + tid;
        int v = (i < N_NODES) ? d_counts[i] : 0;
        int x = v;
#pragma unroll
        for (int o = 1; o < 32; o <<= 1) { int y = __shfl_up_sync(0xffffffffu, x, o); if (lane >= o) x += y; }
        if (lane == 31) wsum[wid] = x;
        __syncthreads();
        if (wid == 0) {
            int s = wsum[lane];
#pragma unroll
            for (int o = 1; o < 32; o <<= 1) { int y = __shfl_up_sync(0xffffffffu, s, o); if (lane >= o) s += y; }
            wsum[lane] = s;
        }
        __syncthreads();
        int warp_excl = (wid > 0) ? wsum[wid - 1] : 0;
        int incl = x + warp_excl;
        int excl = incl - v;
        int carry = s_carry;
        if (i < N_NODES) { int rs = carry + excl; d_rowstart[i] = rs; d_cursor[i] = rs; }
        __syncthreads();
        if (tid == 1023) s_carry = carry + wsum[31];
        __syncthreads();
    }
    if (threadIdx.x == 0) d_rowstart[N_NODES] = s_carry;
}

__global__ void fill_kernel(const int* __restrict__ ei) {
    int e = blockIdx.x * blockDim.x + threadIdx.x;  // E
    int dst = ei[N_EDGES + e];
    int pos = atomicAdd(&d_cursor[dst], 1);
    d_csr_src[pos] = ei[e];
    d_csr_code[pos] = d_code[e];
}

// ---------------- per-layer kernels ----------------
// one warp per node: acc = z[i] + sum relu(z[src] + tab[code]); lane owns 2 cols (float2)
__global__ void __launch_bounds__(256) agg_kernel() {
    int wg = (blockIdx.x * blockDim.x + threadIdx.x) >> 5;
    int lane = threadIdx.x & 31;
    if (wg >= N_NODES) return;
    const float2* zr = (const float2*)(d_z + (size_t)wg * HH);
    float2 acc = __ldg(&zr[lane]);
    int rs = d_rowstart[wg], re = d_rowstart[wg + 1];
    for (int base = rs; base < re; base += 32) {
        int k = base + lane;
        int s = 0, c = 0;
        if (k < re) { s = d_csr_src[k]; c = (int)d_csr_code[k]; }
        int m = re - base; if (m > 32) m = 32;
        for (int j = 0; j < m; j++) {
            int sj = __shfl_sync(0xffffffffu, s, j);
            int cj = __shfl_sync(0xffffffffu, c, j);
            float2 zv = __ldg((const float2*)(d_z + (size_t)sj * HH) + lane);
            float2 tv = __ldg((const float2*)(d_tab + cj * HH) + lane);
            acc.x += fmaxf(zv.x + tv.x, 0.f);
            acc.y += fmaxf(zv.y + tv.y, 0.f);
        }
    }
    ((float2*)(d_hin + (size_t)wg * HH))[lane] = acc;
}

// h1 = hin @ W1 + b1 ; 64 nodes/block, 4 threads per node x 32 cols
__global__ void __launch_bounds__(256) gemm1_kernel(const float* __restrict__ W, const float* __restrict__ b) {
    extern __shared__ __align__(16) char smem_raw[];
    float* Wsh = (float*)smem_raw;          // 64*128
    float* hsh = Wsh + 64 * 128;            // 64*65
    float* bsh = hsh + 64 * 65;             // 128
    int tid = threadIdx.x;
    for (int t = tid; t < 64 * 128; t += 256) Wsh[t] = W[t];
    if (tid < 128) bsh[tid] = b[tid];
    int nb = blockIdx.x * 64;
    for (int t = tid; t < 64 * 64; t += 256) {
        int r = t >> 6, c = t & 63; int n = nb + r;
        hsh[r * 65 + c] = (n < N_NODES) ? d_hin[(size_t)n * HH + c] : 0.f;
    }
    __syncthreads();
    int nl = tid >> 2, q = tid & 3;
    int node = nb + nl;
    ull acc[16];
#pragma unroll
    for (int j = 0; j < 8; j++) {
        float4 bv = *(const float4*)&bsh[q * 32 + 4 * j];
        acc[2 * j] = pack2(bv.x, bv.y); acc[2 * j + 1] = pack2(bv.z, bv.w);
    }
    const float* hr = &hsh[nl * 65];
#pragma unroll 8
    for (int k = 0; k < 64; k++) {
        float a = hr[k];
        ull aa = pack2(a, a);
        const ulonglong2* wr = (const ulonglong2*)&Wsh[k * 128 + q * 32];
#pragma unroll
        for (int j = 0; j < 8; j++) {
            ulonglong2 w = wr[j];
            fma2u(acc[2 * j], aa, w.x);
            fma2u(acc[2 * j + 1], aa, w.y);
        }
    }
    if (node < N_NODES) {
        ulonglong2* op = (ulonglong2*)&d_h1[(size_t)node * 128 + q * 32];
#pragma unroll
        for (int j = 0; j < 8; j++) op[j] = make_ulonglong2(acc[2 * j], acc[2 * j + 1]);
    }
}

__global__ void __launch_bounds__(256) stats128_kernel() {
    int c = threadIdx.x & 127;
    int r = blockIdx.x * 2 + (threadIdx.x >> 7);
    float s = 0.f, s2 = 0.f;
    for (; r < N_NODES; r += gridDim.x * 2) {
        float v = d_h1[(size_t)r * 128 + c];
        s += v; s2 += v * v;
    }
    atomicAdd(&d_ssum[c], s); atomicAdd(&d_ssq[c], s2);
}

__global__ void __launch_bounds__(256) stats64_kernel() {
    int c = threadIdx.x & 63;
    int r = blockIdx.x * 4 + (threadIdx.x >> 6);
    float s = 0.f, s2 = 0.f;
    for (; r < N_NODES; r += gridDim.x * 4) {
        float v = d_h2[(size_t)r * HH + c];
        s += v; s2 += v * v;
    }
    atomicAdd(&d_ssum[c], s); atomicAdd(&d_ssq[c], s2);
}

__global__ void bnfin_kernel(const float* __restrict__ gamma, const float* __restrict__ beta, int C) {
    int c = threadIdx.x;
    if (c < C) {
        float inv = 1.0f / (float)N_NODES;
        float mu = d_ssum[c] * inv;
        float var = d_ssq[c] * inv - mu * mu;
        float r = rsqrtf(var + 1e-5f);
        float sc = gamma[c] * r;
        d_scale[c] = sc;
        d_shift[c] = beta[c] - mu * sc;
        d_ssum[c] = 0.f; d_ssq[c] = 0.f;
    }
}

// h2 = relu(bn1(h1)) @ W2 + b2 ; 64 nodes/block, 4 threads per node x 16 cols
__global__ void __launch_bounds__(256) gemm2_kernel(const float* __restrict__ W, const float* __restrict__ b) {
    extern __shared__ __align__(16) char smem_raw[];
    float* Wsh = (float*)smem_raw;          // 128*64
    float* hsh = Wsh + 128 * 64;            // 64*130
    float* scs = hsh + 64 * 130;            // 128
    float* shs = scs + 128;                 // 128
    float* bsh = shs + 128;                 // 64
    int tid = threadIdx.x;
    for (int t = tid; t < 128 * 64; t += 256) Wsh[t] = W[t];
    if (tid < 128) { scs[tid] = d_scale[tid]; shs[tid] = d_shift[tid]; }
    if (tid < 64) bsh[tid] = b[tid];
    __syncthreads();
    int nb = blockIdx.x * 64;
    for (int t = tid; t < 64 * 128; t += 256) {
        int r = t >> 7, k = t & 127; int n = nb + r;
        float v = (n < N_NODES) ? d_h1[(size_t)n * 128 + k] : 0.f;
        hsh[r * 130 + k] = fmaxf(fmaf(v, scs[k], shs[k]), 0.f);
    }
    __syncthreads();
    int nl = tid >> 2, q = tid & 3;
    int node = nb + nl;
    ull acc[8];
#pragma unroll
    for (int j = 0; j < 4; j++) {
        float4 bv = *(const float4*)&bsh[q * 16 + 4 * j];
        acc[2 * j] = pack2(bv.x, bv.y); acc[2 * j + 1] = pack2(bv.z, bv.w);
    }
    const float* hr = &hsh[nl * 130];
#pragma unroll 8
    for (int k = 0; k < 128; k++) {
        float a = hr[k];
        ull aa = pack2(a, a);
        const ulonglong2* wr = (const ulonglong2*)&Wsh[k * 64 + q * 16];
#pragma unroll
        for (int j = 0; j < 4; j++) {
            ulonglong2 w = wr[j];
            fma2u(acc[2 * j], aa, w.x);
            fma2u(acc[2 * j + 1], aa, w.y);
        }
    }
    if (node < N_NODES) {
        ulonglong2* op = (ulonglong2*)&d_h2[(size_t)node * HH + q * 16];
#pragma unroll
        for (int j = 0; j < 4; j++) op[j] = make_ulonglong2(acc[2 * j], acc[2 * j + 1]);
    }
}

// apply bn2 (+relu if not last layer), write z, write z_cat slice, per-graph sums
__global__ void __launch_bounds__(64) finalize_kernel(const int* __restrict__ batch, float* __restrict__ out,
                                                      int l, int do_relu) {
    int g = blockIdx.x;
    int c = threadIdx.x;
    // lower_bound(g) and lower_bound(g+1)
    int lo = 0, hi = N_NODES;
    while (lo < hi) { int mid = (lo + hi) >> 1; if (batch[mid] < g) lo = mid + 1; else hi = mid; }
    int s = lo;
    lo = s; hi = N_NODES;
    while (lo < hi) { int mid = (lo + hi) >> 1; if (batch[mid] < g + 1) lo = mid + 1; else hi = mid; }
    int e = lo;
    float sc = d_scale[c], sh = d_shift[c];
    float acc = 0.f;
    for (int i = s; i < e; i++) {
        float v = fmaf(d_h2[(size_t)i * HH + c], sc, sh);
        if (do_relu) v = fmaxf(v, 0.f);
        d_z[(size_t)i * HH + c] = v;
        out[(size_t)i * (NL * HH) + l * HH + c] = v;
        acc += v;
    }
    out[(size_t)N_NODES * (NL * HH) + (size_t)g * (NL * HH) + l * HH + c] = acc;
}

// ---------------- launch ----------------
extern "C" void kernel_launch(void* const* d_in, const int* in_sizes, int n_in,
                              void* d_out, int out_size) {
    const int*   x        = (const int*)d_in[0];
    const int*   ei       = (const int*)d_in[1];
    const int*   ea       = (const int*)d_in[2];
    const int*   batch    = (const int*)d_in[3];
    const float* atom_emb = (const float*)d_in[4];
    const float* bond_emb = (const float*)d_in[5];
    const float* W1       = (const float*)d_in[6];
    const float* b1       = (const float*)d_in[7];
    const float* gamma1   = (const float*)d_in[8];
    const float* beta1    = (const float*)d_in[9];
    const float* W2       = (const float*)d_in[10];
    const float* b2       = (const float*)d_in[11];
    const float* gbn      = (const float*)d_in[12];
    const float* bbn      = (const float*)d_in[13];
    float* out = (float*)d_out;

    const int SMEM1 = (64 * 128 + 64 * 65 + 128) * 4;              // 49920
    const int SMEM2 = (128 * 64 + 64 * 130 + 128 + 128 + 64) * 4;  // 67328
    cudaFuncSetAttribute(gemm1_kernel, cudaFuncAttributeMaxDynamicSharedMemorySize, SMEM1);
    cudaFuncSetAttribute(gemm2_kernel, cudaFuncAttributeMaxDynamicSharedMemorySize, SMEM2);

    zero_kernel<<<256, 256>>>();
    tab_kernel<<<512, 64>>>(bond_emb);
    z0_kernel<<<(N_NODES * HH) / 256, 256>>>(x, atom_emb);
    count_kernel<<<N_EDGES / 256, 256>>>(ei, ea);
    scan_kernel<<<1, 1024>>>();
    fill_kernel<<<N_EDGES / 256, 256>>>(ei);

    int gemm_blocks = (N_NODES + 63) / 64;
    for (int l = 0; l < NL; l++) {
        agg_kernel<<<N_NODES / 8, 256>>>();
        gemm1_kernel<<<gemm_blocks, 256, SMEM1>>>(W1 + (size_t)l * 64 * 128, b1 + l * 128);
        stats128_kernel<<<512, 256>>>();
        bnfin_kernel<<<1, 128>>>(gamma1 + l * 128, beta1 + l * 128, 128);
        gemm2_kernel<<<gemm_blocks, 256, SMEM2>>>(W2 + (size_t)l * 128 * 64, b2 + l * 64);
        stats64_kernel<<<512, 256>>>();
        bnfin_kernel<<<1, 64>>>(gbn + l * HH, bbn + l * HH, 64);
        finalize_kernel<<<N_GRAPHS, 64>>>(batch, out, l, (l != NL - 1) ? 1 : 0);
    }
}

// round 2
// speedup vs baseline: 2.5507x; 2.5507x over previous
#include <cuda_runtime.h>
#include <cuda_bf16.h>

#define N_NODES 100000
#define N_EDGES 1280000
#define HH 64
#define NL 5
#define N_GRAPHS 512

typedef unsigned long long ull;

// ---------------- static device scratch ----------------
__device__ __align__(16) float d_z[N_NODES * HH];
__device__ __align__(16) float d_hin[N_NODES * HH];
__device__ __align__(16) float d_h1[N_NODES * 128];
__device__ __align__(16) float d_h2[N_NODES * HH];
__device__ __align__(16) float d_tab[512 * HH];
__device__ int d_counts[N_NODES];
__device__ int d_rowstart[N_NODES + 1];
__device__ int d_cursor[N_NODES];
__device__ int d_csr_src[N_EDGES];
__device__ unsigned short d_code[N_EDGES];
__device__ unsigned short d_csr_code[N_EDGES];
__device__ float d_s1sum[128], d_s1sq[128];
__device__ float d_s2sum[64],  d_s2sq[64];

// ---------------- packed f32x2 helpers ----------------
__device__ __forceinline__ ull pack2(float x, float y) {
    ull r; asm("mov.b64 %0, {%1, %2};" : "=l"(r) : "f"(x), "f"(y)); return r;
}
__device__ __forceinline__ void fma2u(ull &d, ull a, ull b) {
    asm("fma.rn.f32x2 %0, %1, %2, %0;" : "+l"(d) : "l"(a), "l"(b));
}

// ---------------- fused setup: z0 + bond table + zeroing ----------------
__global__ void __launch_bounds__(256) setup_kernel(const int* __restrict__ x,
                                                    const float* __restrict__ atom_emb,
                                                    const float* __restrict__ bond_emb) {
    int bb = blockIdx.x;
    if (bb < 25000) {
        int t = bb * 256 + threadIdx.x;  // N*64
        int n = t >> 6, c = t & 63;
        float s = 0.f;
#pragma unroll
        for (int a = 0; a < 9; a++) {
            int idx = __ldg(&x[n * 9 + a]);
            s += __ldg(&atom_emb[(a * 128 + idx) * HH + c]);
        }
        d_z[t] = s;
    } else if (bb < 25128) {
        int t = (bb - 25000) * 256 + threadIdx.x;  // 512*64
        int q = t >> 6, c = t & 63;
        int a0 = q >> 6, a1 = (q >> 3) & 7, a2 = q & 7;
        d_tab[t] = bond_emb[a0 * HH + c] + bond_emb[(8 + a1) * HH + c] + bond_emb[(16 + a2) * HH + c];
    } else if (bb < 25519) {
        int t = (bb - 25128) * 256 + threadIdx.x;
        if (t < N_NODES) d_counts[t] = 0;
    } else {
        int t = threadIdx.x;
        if (t < 128) { d_s1sum[t] = 0.f; d_s1sq[t] = 0.f; }
        else if (t < 192) { int c = t - 128; d_s2sum[c] = 0.f; d_s2sq[c] = 0.f; }
    }
}

__global__ void count_kernel(const int* __restrict__ ei, const int* __restrict__ ea) {
    int e = blockIdx.x * blockDim.x + threadIdx.x;
    int a0 = ea[e * 3 + 0], a1 = ea[e * 3 + 1], a2 = ea[e * 3 + 2];
    d_code[e] = (unsigned short)((a0 << 6) | (a1 << 3) | a2);
    atomicAdd(&d_counts[ei[N_EDGES + e]], 1);
}

__global__ void scan_kernel() {
    __shared__ int wsum[32];
    __shared__ int s_carry;
    int tid = threadIdx.x, lane = tid & 31, wid = tid >> 5;
    if (tid == 0) s_carry = 0;
    __syncthreads();
    for (int base = 0; base < N_NODES; base += 1024) {
        int i = base + tid;
        int v = (i < N_NODES) ? d_counts[i] : 0;
        int xv = v;
#pragma unroll
        for (int o = 1; o < 32; o <<= 1) { int y = __shfl_up_sync(0xffffffffu, xv, o); if (lane >= o) xv += y; }
        if (lane == 31) wsum[wid] = xv;
        __syncthreads();
        if (wid == 0) {
            int s = wsum[lane];
#pragma unroll
            for (int o = 1; o < 32; o <<= 1) { int y = __shfl_up_sync(0xffffffffu, s, o); if (lane >= o) s += y; }
            wsum[lane] = s;
        }
        __syncthreads();
        int warp_excl = (wid > 0) ? wsum[wid - 1] : 0;
        int excl = xv + warp_excl - v;
        int carry = s_carry;
        if (i < N_NODES) { int rs = carry + excl; d_rowstart[i] = rs; d_cursor[i] = rs; }
        __syncthreads();
        if (tid == 1023) s_carry = carry + wsum[31];
        __syncthreads();
    }
    if (threadIdx.x == 0) d_rowstart[N_NODES] = s_carry;
}

__global__ void fill_kernel(const int* __restrict__ ei) {
    int e = blockIdx.x * blockDim.x + threadIdx.x;
    int dst = ei[N_EDGES + e];
    int pos = atomicAdd(&d_cursor[dst], 1);
    d_csr_src[pos] = ei[e];
    d_csr_code[pos] = d_code[e];
}

// ---------------- per-layer kernels ----------------
// one warp per node; also zeroes this layer's stat buffers (block 0)
__global__ void __launch_bounds__(256) agg_kernel() {
    if (blockIdx.x == 0) {
        int t = threadIdx.x;
        if (t < 128) { d_s1sum[t] = 0.f; d_s1sq[t] = 0.f; }
        else if (t < 192) { int c = t - 128; d_s2sum[c] = 0.f; d_s2sq[c] = 0.f; }
    }
    int wg = (blockIdx.x * blockDim.x + threadIdx.x) >> 5;
    int lane = threadIdx.x & 31;
    if (wg >= N_NODES) return;
    const float2* zr = (const float2*)(d_z + (size_t)wg * HH);
    float2 acc = __ldg(&zr[lane]);
    int rs = d_rowstart[wg], re = d_rowstart[wg + 1];
    for (int base = rs; base < re; base += 32) {
        int k = base + lane;
        int s = 0, c = 0;
        if (k < re) { s = d_csr_src[k]; c = (int)d_csr_code[k]; }
        int m = re - base; if (m > 32) m = 32;
        for (int j = 0; j < m; j++) {
            int sj = __shfl_sync(0xffffffffu, s, j);
            int cj = __shfl_sync(0xffffffffu, c, j);
            float2 zv = __ldg((const float2*)(d_z + (size_t)sj * HH) + lane);
            float2 tv = __ldg((const float2*)(d_tab + cj * HH) + lane);
            acc.x += fmaxf(zv.x + tv.x, 0.f);
            acc.y += fmaxf(zv.y + tv.y, 0.f);
        }
    }
    ((float2*)(d_hin + (size_t)wg * HH))[lane] = acc;
}

// h1 = hin @ W1 + b1 : tile 128 nodes x 128 cols, thread = 2 nodes x 32 cols
// Wsh in 4 padded chunks (stride 2052 floats) -> conflict-free LDS.128
__global__ void __launch_bounds__(256, 2) gemm1_kernel(const float* __restrict__ W, const float* __restrict__ b) {
    extern __shared__ __align__(16) float sm[];
    float* Wsh = sm;              // 4 * 2052 = 8208
    float* hsh = sm + 8208;       // 128 * 65 = 8320
    float* bsh = hsh + 8320;      // 128
    int tid = threadIdx.x;
    for (int t = tid; t < 8192; t += 256) {
        int k = t >> 7, c = t & 127;
        Wsh[(c >> 5) * 2052 + k * 32 + (c & 31)] = W[t];
    }
    if (tid < 128) bsh[tid] = b[tid];
    int nb = blockIdx.x * 128;
    for (int t = tid; t < 8192; t += 256) {
        int r = t >> 6, c = t & 63; int n = nb + r;
        hsh[r * 65 + c] = (n < N_NODES) ? d_hin[(size_t)n * HH + c] : 0.f;
    }
    __syncthreads();
    int np = tid >> 2, q = tid & 3;
    int n0 = nb + np * 2, n1 = n0 + 1;
    ull acc0[16], acc1[16];
#pragma unroll
    for (int j = 0; j < 8; j++) {
        float4 bv = *(const float4*)&bsh[q * 32 + 4 * j];
        acc0[2 * j] = pack2(bv.x, bv.y); acc0[2 * j + 1] = pack2(bv.z, bv.w);
        acc1[2 * j] = acc0[2 * j];       acc1[2 * j + 1] = acc0[2 * j + 1];
    }
    const float* h0 = &hsh[np * 130];
    const float* h1p = h0 + 65;
    const float* wbase = &Wsh[q * 2052];
#pragma unroll 4
    for (int k = 0; k < 64; k++) {
        float x0 = h0[k], x1 = h1p[k];
        ull aa0 = pack2(x0, x0), aa1 = pack2(x1, x1);
        const ulonglong2* wr = (const ulonglong2*)(wbase + k * 32);
#pragma unroll
        for (int j = 0; j < 8; j++) {
            ulonglong2 w = wr[j];
            fma2u(acc0[2 * j], aa0, w.x); fma2u(acc0[2 * j + 1], aa0, w.y);
            fma2u(acc1[2 * j], aa1, w.x); fma2u(acc1[2 * j + 1], aa1, w.y);
        }
    }
    if (n0 < N_NODES) {
        ulonglong2* op = (ulonglong2*)&d_h1[(size_t)n0 * 128 + q * 32];
#pragma unroll
        for (int j = 0; j < 8; j++) op[j] = make_ulonglong2(acc0[2 * j], acc0[2 * j + 1]);
    }
    if (n1 < N_NODES) {
        ulonglong2* op = (ulonglong2*)&d_h1[(size_t)n1 * 128 + q * 32];
#pragma unroll
        for (int j = 0; j < 8; j++) op[j] = make_ulonglong2(acc1[2 * j], acc1[2 * j + 1]);
    }
}

__global__ void __launch_bounds__(256) stats128_kernel() {
    int c = threadIdx.x & 127;
    int r = blockIdx.x * 2 + (threadIdx.x >> 7);
    float s = 0.f, s2 = 0.f;
    for (; r < N_NODES; r += gridDim.x * 2) {
        float v = d_h1[(size_t)r * 128 + c];
        s += v; s2 += v * v;
    }
    atomicAdd(&d_s1sum[c], s); atomicAdd(&d_s1sq[c], s2);
}

__global__ void __launch_bounds__(256) stats64_kernel() {
    int c = threadIdx.x & 63;
    int r = blockIdx.x * 4 + (threadIdx.x >> 6);
    float s = 0.f, s2 = 0.f;
    for (; r < N_NODES; r += gridDim.x * 4) {
        float v = d_h2[(size_t)r * HH + c];
        s += v; s2 += v * v;
    }
    atomicAdd(&d_s2sum[c], s); atomicAdd(&d_s2sq[c], s2);
}

// h2 = relu(bn1(h1)) @ W2 + b2 ; BN1 scale/shift computed inline from raw sums
__global__ void __launch_bounds__(256, 2) gemm2_kernel(const float* __restrict__ W, const float* __restrict__ b,
                                                       const float* __restrict__ gamma, const float* __restrict__ beta) {
    extern __shared__ __align__(16) float sm[];
    float* Wsh = sm;              // 4 * 2052 = 8208
    float* hsh = sm + 8208;       // 128 * 130 = 16640
    float* scs = hsh + 16640;     // 128
    float* shs = scs + 128;       // 128
    float* bsh = shs + 128;       // 64
    int tid = threadIdx.x;
    if (tid < 128) {
        float inv = 1.0f / (float)N_NODES;
        float mu = d_s1sum[tid] * inv;
        float var = d_s1sq[tid] * inv - mu * mu;
        float r = rsqrtf(var + 1e-5f);
        float sc = gamma[tid] * r;
        scs[tid] = sc; shs[tid] = beta[tid] - mu * sc;
    }
    for (int t = tid; t < 8192; t += 256) {
        int k = t >> 6, c = t & 63;
        Wsh[(c >> 4) * 2052 + k * 16 + (c & 15)] = W[t];
    }
    if (tid < 64) bsh[tid] = b[tid];
    __syncthreads();
    int nb = blockIdx.x * 128;
    for (int t = tid; t < 16384; t += 256) {
        int r = t >> 7, k = t & 127; int n = nb + r;
        float v = (n < N_NODES) ? d_h1[(size_t)n * 128 + k] : 0.f;
        hsh[r * 130 + k] = fmaxf(fmaf(v, scs[k], shs[k]), 0.f);
    }
    __syncthreads();
    int np = tid >> 2, q = tid & 3;
    int n0 = nb + np * 2, n1 = n0 + 1;
    ull acc0[8], acc1[8];
#pragma unroll
    for (int j = 0; j < 4; j++) {
        float4 bv = *(const float4*)&bsh[q * 16 + 4 * j];
        acc0[2 * j] = pack2(bv.x, bv.y); acc0[2 * j + 1] = pack2(bv.z, bv.w);
        acc1[2 * j] = acc0[2 * j];       acc1[2 * j + 1] = acc0[2 * j + 1];
    }
    const float* h0 = &hsh[np * 260];
    const float* h1p = h0 + 130;
    const float* wbase = &Wsh[q * 2052];
#pragma unroll 4
    for (int k = 0; k < 128; k++) {
        float x0 = h0[k], x1 = h1p[k];
        ull aa0 = pack2(x0, x0), aa1 = pack2(x1, x1);
        const ulonglong2* wr = (const ulonglong2*)(wbase + k * 16);
#pragma unroll
        for (int j = 0; j < 4; j++) {
            ulonglong2 w = wr[j];
            fma2u(acc0[2 * j], aa0, w.x); fma2u(acc0[2 * j + 1], aa0, w.y);
            fma2u(acc1[2 * j], aa1, w.x); fma2u(acc1[2 * j + 1], aa1, w.y);
        }
    }
    if (n0 < N_NODES) {
        ulonglong2* op = (ulonglong2*)&d_h2[(size_t)n0 * HH + q * 16];
#pragma unroll
        for (int j = 0; j < 4; j++) op[j] = make_ulonglong2(acc0[2 * j], acc0[2 * j + 1]);
    }
    if (n1 < N_NODES) {
        ulonglong2* op = (ulonglong2*)&d_h2[(size_t)n1 * HH + q * 16];
#pragma unroll
        for (int j = 0; j < 4; j++) op[j] = make_ulonglong2(acc1[2 * j], acc1[2 * j + 1]);
    }
}

// BN2 (+relu), write z, z_cat slice, per-graph sums. BN2 scale/shift inline.
__global__ void __launch_bounds__(256) finalize_kernel(const int* __restrict__ batch, float* __restrict__ out,
                                                       const float* __restrict__ gamma, const float* __restrict__ beta,
                                                       int l, int do_relu) {
    __shared__ float sred[4 * 64];
    __shared__ int sbounds[2];
    int g = blockIdx.x;
    int tid = threadIdx.x;
    int c = tid & 63, grp = tid >> 6;
    float inv = 1.0f / (float)N_NODES;
    float mu = d_s2sum[c] * inv;
    float var = d_s2sq[c] * inv - mu * mu;
    float r = rsqrtf(var + 1e-5f);
    float sc = gamma[c] * r;
    float sh = beta[c] - mu * sc;
    if (tid == 0) {
        int lo = 0, hi = N_NODES;
        while (lo < hi) { int m = (lo + hi) >> 1; if (batch[m] < g) lo = m + 1; else hi = m; }
        sbounds[0] = lo;
        hi = N_NODES;
        while (lo < hi) { int m = (lo + hi) >> 1; if (batch[m] <= g) lo = m + 1; else hi = m; }
        sbounds[1] = lo;
    }
    __syncthreads();
    int s = sbounds[0], e = sbounds[1];
    float acc = 0.f;
    for (int i = s + grp; i < e; i += 4) {
        float v = fmaf(d_h2[(size_t)i * HH + c], sc, sh);
        if (do_relu) v = fmaxf(v, 0.f);
        d_z[(size_t)i * HH + c] = v;
        out[(size_t)i * (NL * HH) + l * HH + c] = v;
        acc += v;
    }
    sred[grp * 64 + c] = acc;
    __syncthreads();
    if (grp == 0) {
        float tot = sred[c] + sred[64 + c] + sred[128 + c] + sred[192 + c];
        out[(size_t)N_NODES * (NL * HH) + (size_t)g * (NL * HH) + l * HH + c] = tot;
    }
}

// ---------------- launch ----------------
extern "C" void kernel_launch(void* const* d_in, const int* in_sizes, int n_in,
                              void* d_out, int out_size) {
    const int*   x        = (const int*)d_in[0];
    const int*   ei       = (const int*)d_in[1];
    const int*   ea       = (const int*)d_in[2];
    const int*   batch    = (const int*)d_in[3];
    const float* atom_emb = (const float*)d_in[4];
    const float* bond_emb = (const float*)d_in[5];
    const float* W1       = (const float*)d_in[6];
    const float* b1       = (const float*)d_in[7];
    const float* gamma1   = (const float*)d_in[8];
    const float* beta1    = (const float*)d_in[9];
    const float* W2       = (const float*)d_in[10];
    const float* b2       = (const float*)d_in[11];
    const float* gbn      = (const float*)d_in[12];
    const float* bbn      = (const float*)d_in[13];
    float* out = (float*)d_out;

    const int SMEM1 = (8208 + 8320 + 128) * 4;            // 66624
    const int SMEM2 = (8208 + 16640 + 128 + 128 + 64) * 4; // 100672
    cudaFuncSetAttribute(gemm1_kernel, cudaFuncAttributeMaxDynamicSharedMemorySize, SMEM1);
    cudaFuncSetAttribute(gemm2_kernel, cudaFuncAttributeMaxDynamicSharedMemorySize, SMEM2);

    setup_kernel<<<25520, 256>>>(x, atom_emb, bond_emb);
    count_kernel<<<N_EDGES / 256, 256>>>(ei, ea);
    scan_kernel<<<1, 1024>>>();
    fill_kernel<<<N_EDGES / 256, 256>>>(ei);

    int gemm_blocks = (N_NODES + 127) / 128;
    for (int l = 0; l < NL; l++) {
        agg_kernel<<<N_NODES / 8, 256>>>();
        gemm1_kernel<<<gemm_blocks, 256, SMEM1>>>(W1 + (size_t)l * 64 * 128, b1 + l * 128);
        stats128_kernel<<<512, 256>>>();
        gemm2_kernel<<<gemm_blocks, 256, SMEM2>>>(W2 + (size_t)l * 128 * 64, b2 + l * 64,
                                                  gamma1 + l * 128, beta1 + l * 128);
        stats64_kernel<<<512, 256>>>();
        finalize_kernel<<<N_GRAPHS, 256>>>(batch, out, gbn + l * HH, bbn + l * HH, l, (l != NL - 1) ? 1 : 0);
    }
}